// round 8
// baseline (speedup 1.0000x reference)
#include <cuda_runtime.h>
#include <cuda_bf16.h>
#include <math.h>
#include <stdint.h>

// Problem constants
#define NTOK   2048
#define HID    2048
#define INTER_ 1024
#define NEXP   8
#define TOPK   2
#define NSLOT  (NTOK * TOPK)

// MMA tiling: block 128x128 C, 8 warps (2x4), warp 64x32, k-tile 32 (bf16)
#define KT    32
#define ROWB  80
#define ROWW  20
#define TILE  10240
#define SM_BUF 1024
#define SM_AH(b) (SM_BUF + (b) * 4 * TILE)
#define SM_AL(b) (SM_AH(b) + TILE)
#define SM_BH(b) (SM_AH(b) + 2 * TILE)
#define SM_BL(b) (SM_AH(b) + 3 * TILE)
#define SM_TOTAL (SM_BUF + 8 * TILE)     // 82944
#define CS_STRIDE 132

// -------- device scratch --------
__device__ int   g_counts[NEXP];
__device__ int   g_offsets[NEXP];
__device__ int   g_token[NSLOT];
__device__ int   g_pos[NSLOT];          // slot -> sorted position
__device__ float g_weight[NSLOT];
__device__ float g_dout[(size_t)NSLOT * HID];   // dense down output per slot (32MB)
// hi/lo bf16 planes
__device__ __nv_bfloat16 g_xh[(size_t)NTOK * HID];
__device__ __nv_bfloat16 g_xl[(size_t)NTOK * HID];
__device__ __nv_bfloat16 g_gh[(size_t)NEXP * INTER_ * HID];
__device__ __nv_bfloat16 g_gl[(size_t)NEXP * INTER_ * HID];
__device__ __nv_bfloat16 g_uh[(size_t)NEXP * INTER_ * HID];
__device__ __nv_bfloat16 g_ul[(size_t)NEXP * INTER_ * HID];
__device__ __nv_bfloat16 g_dh[(size_t)NEXP * HID * INTER_];
__device__ __nv_bfloat16 g_dl[(size_t)NEXP * HID * INTER_];
__device__ __nv_bfloat16 g_ih[(size_t)NSLOT * INTER_];
__device__ __nv_bfloat16 g_il[(size_t)NSLOT * INTER_];

// ---------------- helpers ----------------
__device__ __forceinline__ uint32_t smem_u32(const void* p) {
    uint32_t a;
    asm("{ .reg .u64 t; cvta.to.shared.u64 t, %1; cvt.u32.u64 %0, t; }" : "=r"(a) : "l"(p));
    return a;
}
#define CP16(sm, gm) asm volatile("cp.async.cg.shared.global [%0], [%1], 16;" :: "r"(sm), "l"(gm))
#define CP_COMMIT()  asm volatile("cp.async.commit_group;" ::: "memory")
#define CP_WAIT(n)   asm volatile("cp.async.wait_group %0;" :: "n"(n) : "memory")

__device__ __forceinline__ void mma_bf16(float* c, const uint32_t* a, const uint32_t* b) {
    asm volatile(
        "mma.sync.aligned.m16n8k16.row.col.f32.bf16.bf16.f32 "
        "{%0,%1,%2,%3}, {%4,%5,%6,%7}, {%8,%9}, {%0,%1,%2,%3};\n"
        : "+f"(c[0]), "+f"(c[1]), "+f"(c[2]), "+f"(c[3])
        : "r"(a[0]), "r"(a[1]), "r"(a[2]), "r"(a[3]), "r"(b[0]), "r"(b[1]));
}
__device__ __forceinline__ void ldm_x4(uint32_t* r, uint32_t addr) {
    asm volatile("ldmatrix.sync.aligned.m8n8.x4.shared.b16 {%0,%1,%2,%3}, [%4];"
        : "=r"(r[0]), "=r"(r[1]), "=r"(r[2]), "=r"(r[3]) : "r"(addr));
}

__device__ __forceinline__ uint32_t packhl(float a, float b, float& ra, float& rb) {
    __nv_bfloat16 ha = __float2bfloat16(a);
    __nv_bfloat16 hb = __float2bfloat16(b);
    ra = a - __bfloat162float(ha);
    rb = b - __bfloat162float(hb);
    __nv_bfloat162 p = __halves2bfloat162(ha, hb);
    return *reinterpret_cast<uint32_t*>(&p);
}
__device__ __forceinline__ uint32_t packlo(float a, float b) {
    __nv_bfloat162 p = __halves2bfloat162(__float2bfloat16(a), __float2bfloat16(b));
    return *reinterpret_cast<uint32_t*>(&p);
}

// ---------------- split: fp32 -> hi/lo bf16 planes ----------------
__global__ void split_kernel(const float4* __restrict__ src,
                             uint2* __restrict__ hi, uint2* __restrict__ lo, int n4) {
    int i = blockIdx.x * blockDim.x + threadIdx.x;
    if (i >= n4) return;
    float4 v = src[i];
    float rx, ry, rz, rw;
    uint2 H, L;
    H.x = packhl(v.x, v.y, rx, ry);
    H.y = packhl(v.z, v.w, rz, rw);
    L.x = packlo(rx, ry);
    L.y = packlo(rz, rw);
    hi[i] = H;
    lo[i] = L;
}
// fused split for two tensors of equal size (gate + up)
__global__ void split2_kernel(const float4* __restrict__ s0, uint2* __restrict__ h0, uint2* __restrict__ l0,
                              const float4* __restrict__ s1, uint2* __restrict__ h1, uint2* __restrict__ l1,
                              int n4) {
    int i = blockIdx.x * blockDim.x + threadIdx.x;
    const float4* src; uint2 *hi, *lo; int j;
    if (i < n4)          { src = s0; hi = h0; lo = l0; j = i; }
    else if (i < 2 * n4) { src = s1; hi = h1; lo = l1; j = i - n4; }
    else return;
    float4 v = src[j];
    float rx, ry, rz, rw;
    uint2 H, L;
    H.x = packhl(v.x, v.y, rx, ry);
    H.y = packhl(v.z, v.w, rz, rw);
    L.x = packlo(rx, ry);
    L.y = packlo(rz, rw);
    hi[j] = H;
    lo[j] = L;
}

// ---------------- routing ----------------
__global__ void route_kernel(const int* __restrict__ idxw,
                             const float* __restrict__ wts) {
    __shared__ int cnt[NEXP], off[NEXP], cur[NEXP];
    __shared__ int not64;
    int tid = threadIdx.x;
    if (tid < NEXP) { cnt[tid] = 0; cur[tid] = 0; }
    if (tid == 0) not64 = 0;
    __syncthreads();
    int any = 0;
    for (int i = 2 * tid + 1; i < NSLOT; i += 2 * blockDim.x) any |= idxw[i];
    if (any) atomicOr(&not64, 1);
    __syncthreads();
    const int is64 = !not64;
    for (int s = tid; s < NSLOT; s += blockDim.x) {
        int e = is64 ? idxw[2 * s] : idxw[s];
        atomicAdd(&cnt[e], 1);
    }
    __syncthreads();
    if (tid == 0) {
        int acc = 0;
        for (int e = 0; e < NEXP; e++) {
            off[e] = acc; g_offsets[e] = acc; g_counts[e] = cnt[e];
            acc += cnt[e];
        }
    }
    __syncthreads();
    for (int s = tid; s < NSLOT; s += blockDim.x) {
        int e = is64 ? idxw[2 * s] : idxw[s];
        int p = off[e] + atomicAdd(&cur[e], 1);
        g_token[p]  = s >> 1;
        g_weight[p] = wts[s];
        g_pos[s]    = p;
    }
}

// ---------------- gather: out[t] = dout[pos(2t)] + dout[pos(2t+1)] ----------
__global__ void gather_kernel(float4* __restrict__ out) {
    int i = blockIdx.x * blockDim.x + threadIdx.x;       // over NTOK*HID/4
    if (i >= NTOK * HID / 4) return;
    int t = i / (HID / 4);
    int h = i - t * (HID / 4);
    const float4* r0 = (const float4*)(g_dout + (size_t)g_pos[2 * t] * HID) + h;
    const float4* r1 = (const float4*)(g_dout + (size_t)g_pos[2 * t + 1] * HID) + h;
    float4 a = *r0, b = *r1;
    out[i] = make_float4(a.x + b.x, a.y + b.y, a.z + b.z, a.w + b.w);
}

// ---------------- GEMM 1: gate+up, 3x-bf16 mma, ldmatrix fragments --------
__global__ __launch_bounds__(256, 2)
void gemm_gu_mma(void) {
    const int e   = blockIdx.z;
    const int cnt = g_counts[e];
    const int m0  = blockIdx.y * 128;
    if (m0 >= cnt) return;
    const int base = g_offsets[e];
    const int n0   = blockIdx.x * 64;

    extern __shared__ char smem[];
    const uint32_t sb = smem_u32(smem);
    int*   sTok = (int*)smem;
    float* sW   = (float*)(smem + 512);

    const int tid  = threadIdx.x;
    const int wid  = tid >> 5;
    const int lane = tid & 31;

    if (tid < 128) {
        int m = m0 + tid;
        int r = base + (m < cnt ? m : cnt - 1);
        sTok[tid] = g_token[r];
        sW[tid]   = (m < cnt) ? g_weight[r] : 0.f;
    }
    __syncthreads();

    const int lrow  = tid >> 1;
    const int lhalf = tid & 1;
    const __nv_bfloat16* aRowH = g_xh + (size_t)sTok[lrow] * HID;
    const __nv_bfloat16* aRowL = g_xl + (size_t)sTok[lrow] * HID;
    const __nv_bfloat16* bRowH = (lrow < 64)
        ? g_gh + ((size_t)e * INTER_ + n0 + lrow) * HID
        : g_uh + ((size_t)e * INTER_ + n0 + lrow - 64) * HID;
    const __nv_bfloat16* bRowL = (lrow < 64)
        ? g_gl + ((size_t)e * INTER_ + n0 + lrow) * HID
        : g_ul + ((size_t)e * INTER_ + n0 + lrow - 64) * HID;
    const uint32_t roff = (uint32_t)(lrow * ROWB + lhalf * 32);

    const int wm = wid >> 2, wn = wid & 3;
    const int g  = lane >> 2, t4 = lane & 3;

    const int lg = lane >> 3;
    const int lr7 = lane & 7;
    uint32_t aoff[4], boff[2];
    #pragma unroll
    for (int mt = 0; mt < 4; mt++)
        aoff[mt] = (uint32_t)((wm * 64 + mt * 16 + (lg & 1) * 8 + lr7) * ROWB + (lg >> 1) * 16);
    #pragma unroll
    for (int p = 0; p < 2; p++)
        boff[p] = (uint32_t)((wn * 32 + (2 * p + (lg >> 1)) * 8 + lr7) * ROWB + (lg & 1) * 16);

    float acc[4][4][4];
    #pragma unroll
    for (int i = 0; i < 4; i++)
        #pragma unroll
        for (int j = 0; j < 4; j++)
            #pragma unroll
            for (int r = 0; r < 4; r++) acc[i][j][r] = 0.f;

    const int NT = HID / KT;   // 64

    {
        const int src = lhalf * 16;
        CP16(sb + SM_AH(0) + roff,      aRowH + src);
        CP16(sb + SM_AH(0) + roff + 16, aRowH + src + 8);
        CP16(sb + SM_AL(0) + roff,      aRowL + src);
        CP16(sb + SM_AL(0) + roff + 16, aRowL + src + 8);
        CP16(sb + SM_BH(0) + roff,      bRowH + src);
        CP16(sb + SM_BH(0) + roff + 16, bRowH + src + 8);
        CP16(sb + SM_BL(0) + roff,      bRowL + src);
        CP16(sb + SM_BL(0) + roff + 16, bRowL + src + 8);
        CP_COMMIT();
    }

    for (int t = 0; t < NT; t++) {
        if (t + 1 < NT) {
            const int b = (t + 1) & 1;
            const int src = (t + 1) * KT + lhalf * 16;
            CP16(sb + SM_AH(b) + roff,      aRowH + src);
            CP16(sb + SM_AH(b) + roff + 16, aRowH + src + 8);
            CP16(sb + SM_AL(b) + roff,      aRowL + src);
            CP16(sb + SM_AL(b) + roff + 16, aRowL + src + 8);
            CP16(sb + SM_BH(b) + roff,      bRowH + src);
            CP16(sb + SM_BH(b) + roff + 16, bRowH + src + 8);
            CP16(sb + SM_BL(b) + roff,      bRowL + src);
            CP16(sb + SM_BL(b) + roff + 16, bRowL + src + 8);
            CP_COMMIT();
            CP_WAIT(1);
        } else {
            CP_WAIT(0);
        }
        __syncthreads();

        const int buf = t & 1;
        const uint32_t ahb = sb + SM_AH(buf);
        const uint32_t alb = sb + SM_AL(buf);
        const uint32_t bhb = sb + SM_BH(buf);
        const uint32_t blb = sb + SM_BL(buf);
        #pragma unroll
        for (int ks = 0; ks < 2; ks++) {
            const uint32_t ko = ks * 32;
            uint32_t bh[2][4], bl[2][4];
            ldm_x4(bh[0], bhb + boff[0] + ko);
            ldm_x4(bh[1], bhb + boff[1] + ko);
            ldm_x4(bl[0], blb + boff[0] + ko);
            ldm_x4(bl[1], blb + boff[1] + ko);
            #pragma unroll
            for (int mt = 0; mt < 4; mt++) {
                uint32_t ah[4], al[4];
                ldm_x4(ah, ahb + aoff[mt] + ko);
                ldm_x4(al, alb + aoff[mt] + ko);
                #pragma unroll
                for (int nt = 0; nt < 4; nt++) {
                    const uint32_t* BH = &bh[nt >> 1][(nt & 1) * 2];
                    const uint32_t* BL = &bl[nt >> 1][(nt & 1) * 2];
                    mma_bf16(acc[mt][nt], al, BH);
                    mma_bf16(acc[mt][nt], ah, BL);
                    mma_bf16(acc[mt][nt], ah, BH);
                }
            }
        }
        __syncthreads();
    }

    // stage accumulators to smem, SwiGLU-combine, split to hi/lo planes
    float* Cs = (float*)(smem + SM_BUF);
    #pragma unroll
    for (int mt = 0; mt < 4; mt++) {
        #pragma unroll
        for (int nt = 0; nt < 4; nt++) {
            int row = wm * 64 + mt * 16 + g;
            int col = wn * 32 + nt * 8 + t4 * 2;
            *reinterpret_cast<float2*>(&Cs[row * CS_STRIDE + col]) =
                make_float2(acc[mt][nt][0], acc[mt][nt][1]);
            *reinterpret_cast<float2*>(&Cs[(row + 8) * CS_STRIDE + col]) =
                make_float2(acc[mt][nt][2], acc[mt][nt][3]);
        }
    }
    __syncthreads();

    const int jj = (tid & 15) * 4;
    const int rb = (tid >> 4) * 8;
    #pragma unroll
    for (int mm = 0; mm < 8; mm++) {
        int m = rb + mm;
        if (m0 + m >= cnt) continue;
        float w = sW[m];
        float4 gv = *reinterpret_cast<const float4*>(&Cs[m * CS_STRIDE + jj]);
        float4 uv = *reinterpret_cast<const float4*>(&Cs[m * CS_STRIDE + 64 + jj]);
        float o0 = (gv.x / (1.f + __expf(-gv.x))) * uv.x * w;
        float o1 = (gv.y / (1.f + __expf(-gv.y))) * uv.y * w;
        float o2 = (gv.z / (1.f + __expf(-gv.z))) * uv.z * w;
        float o3 = (gv.w / (1.f + __expf(-gv.w))) * uv.w * w;
        float r0, r1, r2, r3;
        uint2 H, L;
        H.x = packhl(o0, o1, r0, r1);
        H.y = packhl(o2, o3, r2, r3);
        L.x = packlo(r0, r1);
        L.y = packlo(r2, r3);
        size_t idx = (size_t)(base + m0 + m) * INTER_ + n0 + jj;
        *reinterpret_cast<uint2*>(&g_ih[idx]) = H;
        *reinterpret_cast<uint2*>(&g_il[idx]) = L;
    }
}

// ---------------- GEMM 2: down, 3x-bf16 mma, dense store -----------------
__global__ __launch_bounds__(256, 2)
void gemm_down_mma(void) {
    const int e   = blockIdx.z;
    const int cnt = g_counts[e];
    const int m0  = blockIdx.y * 128;
    if (m0 >= cnt) return;
    const int base = g_offsets[e];
    const int n0   = blockIdx.x * 128;

    extern __shared__ char smem[];
    const uint32_t sb = smem_u32(smem);

    const int tid  = threadIdx.x;
    const int wid  = tid >> 5;
    const int lane = tid & 31;

    const int lrow  = tid >> 1;
    const int lhalf = tid & 1;
    int ar = base + m0 + lrow; if (ar > NSLOT - 1) ar = NSLOT - 1;
    const __nv_bfloat16* aRowH = g_ih + (size_t)ar * INTER_;
    const __nv_bfloat16* aRowL = g_il + (size_t)ar * INTER_;
    const __nv_bfloat16* bRowH = g_dh + ((size_t)e * HID + n0 + lrow) * INTER_;
    const __nv_bfloat16* bRowL = g_dl + ((size_t)e * HID + n0 + lrow) * INTER_;
    const uint32_t roff = (uint32_t)(lrow * ROWB + lhalf * 32);

    const int wm = wid >> 2, wn = wid & 3;
    const int g  = lane >> 2, t4 = lane & 3;

    const int lg = lane >> 3;
    const int lr7 = lane & 7;
    uint32_t aoff[4], boff[2];
    #pragma unroll
    for (int mt = 0; mt < 4; mt++)
        aoff[mt] = (uint32_t)((wm * 64 + mt * 16 + (lg & 1) * 8 + lr7) * ROWB + (lg >> 1) * 16);
    #pragma unroll
    for (int p = 0; p < 2; p++)
        boff[p] = (uint32_t)((wn * 32 + (2 * p + (lg >> 1)) * 8 + lr7) * ROWB + (lg & 1) * 16);

    float acc[4][4][4];
    #pragma unroll
    for (int i = 0; i < 4; i++)
        #pragma unroll
        for (int j = 0; j < 4; j++)
            #pragma unroll
            for (int r = 0; r < 4; r++) acc[i][j][r] = 0.f;

    const int NT = INTER_ / KT;   // 32

    {
        const int src = lhalf * 16;
        CP16(sb + SM_AH(0) + roff,      aRowH + src);
        CP16(sb + SM_AH(0) + roff + 16, aRowH + src + 8);
        CP16(sb + SM_AL(0) + roff,      aRowL + src);
        CP16(sb + SM_AL(0) + roff + 16, aRowL + src + 8);
        CP16(sb + SM_BH(0) + roff,      bRowH + src);
        CP16(sb + SM_BH(0) + roff + 16, bRowH + src + 8);
        CP16(sb + SM_BL(0) + roff,      bRowL + src);
        CP16(sb + SM_BL(0) + roff + 16, bRowL + src + 8);
        CP_COMMIT();
    }

    for (int t = 0; t < NT; t++) {
        if (t + 1 < NT) {
            const int b = (t + 1) & 1;
            const int src = (t + 1) * KT + lhalf * 16;
            CP16(sb + SM_AH(b) + roff,      aRowH + src);
            CP16(sb + SM_AH(b) + roff + 16, aRowH + src + 8);
            CP16(sb + SM_AL(b) + roff,      aRowL + src);
            CP16(sb + SM_AL(b) + roff + 16, aRowL + src + 8);
            CP16(sb + SM_BH(b) + roff,      bRowH + src);
            CP16(sb + SM_BH(b) + roff + 16, bRowH + src + 8);
            CP16(sb + SM_BL(b) + roff,      bRowL + src);
            CP16(sb + SM_BL(b) + roff + 16, bRowL + src + 8);
            CP_COMMIT();
            CP_WAIT(1);
        } else {
            CP_WAIT(0);
        }
        __syncthreads();

        const int buf = t & 1;
        const uint32_t ahb = sb + SM_AH(buf);
        const uint32_t alb = sb + SM_AL(buf);
        const uint32_t bhb = sb + SM_BH(buf);
        const uint32_t blb = sb + SM_BL(buf);
        #pragma unroll
        for (int ks = 0; ks < 2; ks++) {
            const uint32_t ko = ks * 32;
            uint32_t bh[2][4], bl[2][4];
            ldm_x4(bh[0], bhb + boff[0] + ko);
            ldm_x4(bh[1], bhb + boff[1] + ko);
            ldm_x4(bl[0], blb + boff[0] + ko);
            ldm_x4(bl[1], blb + boff[1] + ko);
            #pragma unroll
            for (int mt = 0; mt < 4; mt++) {
                uint32_t ah[4], al[4];
                ldm_x4(ah, ahb + aoff[mt] + ko);
                ldm_x4(al, alb + aoff[mt] + ko);
                #pragma unroll
                for (int nt = 0; nt < 4; nt++) {
                    const uint32_t* BH = &bh[nt >> 1][(nt & 1) * 2];
                    const uint32_t* BL = &bl[nt >> 1][(nt & 1) * 2];
                    mma_bf16(acc[mt][nt], al, BH);
                    mma_bf16(acc[mt][nt], ah, BL);
                    mma_bf16(acc[mt][nt], ah, BH);
                }
            }
        }
        __syncthreads();
    }

    // dense store to g_dout (sorted slot order) — no atomics
    #pragma unroll
    for (int mt = 0; mt < 4; mt++) {
        int row0 = wm * 64 + mt * 16 + g;
        int row1 = row0 + 8;
        bool v0 = (m0 + row0 < cnt);
        bool v1 = (m0 + row1 < cnt);
        float* o0 = g_dout + (size_t)(base + m0 + row0) * HID + n0;
        float* o1 = g_dout + (size_t)(base + m0 + row1) * HID + n0;
        #pragma unroll
        for (int nt = 0; nt < 4; nt++) {
            int col = wn * 32 + nt * 8 + t4 * 2;
            if (v0) *reinterpret_cast<float2*>(&o0[col]) =
                        make_float2(acc[mt][nt][0], acc[mt][nt][1]);
            if (v1) *reinterpret_cast<float2*>(&o1[col]) =
                        make_float2(acc[mt][nt][2], acc[mt][nt][3]);
        }
    }
}

// ---------------- launch ----------------
extern "C" void kernel_launch(void* const* d_in, const int* in_sizes, int n_in,
                              void* d_out, int out_size) {
    const float* x    = (const float*)d_in[0];
    const int*   idxw = (const int*)d_in[1];
    const float* wts  = (const float*)d_in[2];
    const float* gate = (const float*)d_in[3];
    const float* up   = (const float*)d_in[4];
    const float* down = (const float*)d_in[5];
    float* out = (float*)d_out;

    cudaFuncSetAttribute(gemm_gu_mma,   cudaFuncAttributeMaxDynamicSharedMemorySize, SM_TOTAL);
    cudaFuncSetAttribute(gemm_down_mma, cudaFuncAttributeMaxDynamicSharedMemorySize, SM_TOTAL);

    __nv_bfloat16 *xh, *xl, *gh, *gl, *uh, *ul, *dh, *dl;
    cudaGetSymbolAddress((void**)&xh, g_xh);
    cudaGetSymbolAddress((void**)&xl, g_xl);
    cudaGetSymbolAddress((void**)&gh, g_gh);
    cudaGetSymbolAddress((void**)&gl, g_gl);
    cudaGetSymbolAddress((void**)&uh, g_uh);
    cudaGetSymbolAddress((void**)&ul, g_ul);
    cudaGetSymbolAddress((void**)&dh, g_dh);
    cudaGetSymbolAddress((void**)&dl, g_dl);

    // launch order: route(1) splitX(2) split_gu(3) split_down(4) gu(5) down(6) gather(7)
    // -> ncu -s 5 -c 1 profiles gemm_down_mma
    route_kernel<<<1, 256>>>(idxw, wts);
    {
        int nx = NTOK * HID / 4;
        split_kernel<<<(nx + 255) / 256, 256>>>((const float4*)x, (uint2*)xh, (uint2*)xl, nx);
        int nw = NEXP * INTER_ * HID / 4;
        split2_kernel<<<(2 * nw + 255) / 256, 256>>>(
            (const float4*)gate, (uint2*)gh, (uint2*)gl,
            (const float4*)up,   (uint2*)uh, (uint2*)ul, nw);
        split_kernel<<<(nw + 255) / 256, 256>>>((const float4*)down, (uint2*)dh, (uint2*)dl, nw);
    }
    {
        dim3 grid(INTER_ / 64, NSLOT / 128, NEXP);
        gemm_gu_mma<<<grid, 256, SM_TOTAL>>>();
    }
    {
        dim3 grid(HID / 128, NSLOT / 128, NEXP);
        gemm_down_mma<<<grid, 256, SM_TOTAL>>>();
    }
    {
        int ng = NTOK * HID / 4;
        gather_kernel<<<(ng + 255) / 256, 256>>>((float4*)out);
    }
}

// round 9
// speedup vs baseline: 1.1133x; 1.1133x over previous
#include <cuda_runtime.h>
#include <cuda_bf16.h>
#include <math.h>
#include <stdint.h>

// Problem constants
#define NTOK   2048
#define HID    2048
#define INTER_ 1024
#define NEXP   8
#define TOPK   2
#define NSLOT  (NTOK * TOPK)

// MMA tiling: block 128x128 C, 8 warps (2x4), warp 64x32, k-tile 32 (bf16)
// SMEM: 3-stage, XOR-swizzled 64B rows (no padding), 4 planes per stage.
#define KT     32
#define PLANE  8192                 // 128 rows * 64B
#define STAGE  (4 * PLANE)          // AH, AL, BH, BL
#define SM_BUF 1024
#define SLOT(s) (SM_BUF + (s) * STAGE)
#define SM_TOTAL (SM_BUF + 3 * STAGE)   // 99328
#define CS_STRIDE 132

// -------- device scratch --------
__device__ int   g_counts[NEXP];
__device__ int   g_offsets[NEXP];
__device__ int   g_token[NSLOT];
__device__ int   g_pos[NSLOT];
__device__ float g_weight[NSLOT];
__device__ float g_dout[(size_t)NSLOT * HID];
__device__ __nv_bfloat16 g_xh[(size_t)NTOK * HID];
__device__ __nv_bfloat16 g_xl[(size_t)NTOK * HID];
__device__ __nv_bfloat16 g_gh[(size_t)NEXP * INTER_ * HID];
__device__ __nv_bfloat16 g_gl[(size_t)NEXP * INTER_ * HID];
__device__ __nv_bfloat16 g_uh[(size_t)NEXP * INTER_ * HID];
__device__ __nv_bfloat16 g_ul[(size_t)NEXP * INTER_ * HID];
__device__ __nv_bfloat16 g_dh[(size_t)NEXP * HID * INTER_];
__device__ __nv_bfloat16 g_dl[(size_t)NEXP * HID * INTER_];
__device__ __nv_bfloat16 g_ih[(size_t)NSLOT * INTER_];
__device__ __nv_bfloat16 g_il[(size_t)NSLOT * INTER_];

// ---------------- helpers ----------------
__device__ __forceinline__ uint32_t smem_u32(const void* p) {
    uint32_t a;
    asm("{ .reg .u64 t; cvta.to.shared.u64 t, %1; cvt.u32.u64 %0, t; }" : "=r"(a) : "l"(p));
    return a;
}
#define CP16(sm, gm) asm volatile("cp.async.cg.shared.global [%0], [%1], 16;" :: "r"(sm), "l"(gm))
#define CP_COMMIT()  asm volatile("cp.async.commit_group;" ::: "memory")
#define CP_WAIT(n)   asm volatile("cp.async.wait_group %0;" :: "n"(n) : "memory")

__device__ __forceinline__ void mma_bf16(float* c, const uint32_t* a, const uint32_t* b) {
    asm volatile(
        "mma.sync.aligned.m16n8k16.row.col.f32.bf16.bf16.f32 "
        "{%0,%1,%2,%3}, {%4,%5,%6,%7}, {%8,%9}, {%0,%1,%2,%3};\n"
        : "+f"(c[0]), "+f"(c[1]), "+f"(c[2]), "+f"(c[3])
        : "r"(a[0]), "r"(a[1]), "r"(a[2]), "r"(a[3]), "r"(b[0]), "r"(b[1]));
}
__device__ __forceinline__ void ldm_x4(uint32_t* r, uint32_t addr) {
    asm volatile("ldmatrix.sync.aligned.m8n8.x4.shared.b16 {%0,%1,%2,%3}, [%4];"
        : "=r"(r[0]), "=r"(r[1]), "=r"(r[2]), "=r"(r[3]) : "r"(addr));
}

// swizzled byte offset within a plane: 64B rows, 16B chunks, chunk ^= (row>>1)&3
__device__ __forceinline__ uint32_t swz(int row, int chunk) {
    return (uint32_t)((row << 6) + (((chunk ^ ((row >> 1) & 3))) << 4));
}

__device__ __forceinline__ uint32_t packhl(float a, float b, float& ra, float& rb) {
    __nv_bfloat16 ha = __float2bfloat16(a);
    __nv_bfloat16 hb = __float2bfloat16(b);
    ra = a - __bfloat162float(ha);
    rb = b - __bfloat162float(hb);
    __nv_bfloat162 p = __halves2bfloat162(ha, hb);
    return *reinterpret_cast<uint32_t*>(&p);
}
__device__ __forceinline__ uint32_t packlo(float a, float b) {
    __nv_bfloat162 p = __halves2bfloat162(__float2bfloat16(a), __float2bfloat16(b));
    return *reinterpret_cast<uint32_t*>(&p);
}

// ---------------- fused split: all weights + x ----------------
__global__ void split_all(const float4* __restrict__ xs,
                          const float4* __restrict__ gs,
                          const float4* __restrict__ us,
                          const float4* __restrict__ ds,
                          uint2* __restrict__ xh, uint2* __restrict__ xl,
                          uint2* __restrict__ gh, uint2* __restrict__ gl,
                          uint2* __restrict__ uh, uint2* __restrict__ ul,
                          uint2* __restrict__ dh, uint2* __restrict__ dl) {
    const int nw = NEXP * INTER_ * HID / 4;
    const int nx = NTOK * HID / 4;
    int i = blockIdx.x * blockDim.x + threadIdx.x;
    const float4* src; uint2 *H, *L; int j;
    if (i < nw)               { src = gs; H = gh; L = gl; j = i; }
    else if (i < 2 * nw)      { src = us; H = uh; L = ul; j = i - nw; }
    else if (i < 3 * nw)      { src = ds; H = dh; L = dl; j = i - 2 * nw; }
    else if (i < 3 * nw + nx) { src = xs; H = xh; L = xl; j = i - 3 * nw; }
    else return;
    float4 v = src[j];
    float rx, ry, rz, rw;
    uint2 Hv, Lv;
    Hv.x = packhl(v.x, v.y, rx, ry);
    Hv.y = packhl(v.z, v.w, rz, rw);
    Lv.x = packlo(rx, ry);
    Lv.y = packlo(rz, rw);
    H[j] = Hv;
    L[j] = Lv;
}

// ---------------- routing ----------------
__global__ void route_kernel(const int* __restrict__ idxw,
                             const float* __restrict__ wts) {
    __shared__ int cnt[NEXP], off[NEXP], cur[NEXP];
    __shared__ int not64;
    int tid = threadIdx.x;
    if (tid < NEXP) { cnt[tid] = 0; cur[tid] = 0; }
    if (tid == 0) not64 = 0;
    __syncthreads();
    int any = 0;
    for (int i = 2 * tid + 1; i < NSLOT; i += 2 * blockDim.x) any |= idxw[i];
    if (any) atomicOr(&not64, 1);
    __syncthreads();
    const int is64 = !not64;
    for (int s = tid; s < NSLOT; s += blockDim.x) {
        int e = is64 ? idxw[2 * s] : idxw[s];
        atomicAdd(&cnt[e], 1);
    }
    __syncthreads();
    if (tid == 0) {
        int acc = 0;
        for (int e = 0; e < NEXP; e++) {
            off[e] = acc; g_offsets[e] = acc; g_counts[e] = cnt[e];
            acc += cnt[e];
        }
    }
    __syncthreads();
    for (int s = tid; s < NSLOT; s += blockDim.x) {
        int e = is64 ? idxw[2 * s] : idxw[s];
        int p = off[e] + atomicAdd(&cur[e], 1);
        g_token[p]  = s >> 1;
        g_weight[p] = wts[s];
        g_pos[s]    = p;
    }
}

// ---------------- gather: out[t] = dout[pos(2t)] + dout[pos(2t+1)] ---------
__global__ void gather_kernel(float4* __restrict__ out) {
    int i = blockIdx.x * blockDim.x + threadIdx.x;
    if (i >= NTOK * HID / 4) return;
    int t = i / (HID / 4);
    int h = i - t * (HID / 4);
    const float4* r0 = (const float4*)(g_dout + (size_t)g_pos[2 * t] * HID) + h;
    const float4* r1 = (const float4*)(g_dout + (size_t)g_pos[2 * t + 1] * HID) + h;
    float4 a = *r0, b = *r1;
    out[i] = make_float4(a.x + b.x, a.y + b.y, a.z + b.z, a.w + b.w);
}

// ---------------- GEMM 1: gate+up, 3x-bf16, 3-stage pipeline --------------
__global__ __launch_bounds__(256, 2)
void gemm_gu_mma(void) {
    const int e   = blockIdx.z;
    const int cnt = g_counts[e];
    const int m0  = blockIdx.y * 128;
    if (m0 >= cnt) return;
    const int base = g_offsets[e];
    const int n0   = blockIdx.x * 64;

    extern __shared__ char smem[];
    const uint32_t sb = smem_u32(smem);
    int*   sTok = (int*)smem;
    float* sW   = (float*)(smem + 512);

    const int tid  = threadIdx.x;
    const int wid  = tid >> 5;
    const int lane = tid & 31;

    if (tid < 128) {
        int m = m0 + tid;
        int r = base + (m < cnt ? m : cnt - 1);
        sTok[tid] = g_token[r];
        sW[tid]   = (m < cnt) ? g_weight[r] : 0.f;
    }
    __syncthreads();

    // loader: lrow covers 128 rows, lhalf selects 32B half (2 chunks)
    const int lrow  = tid >> 1;
    const int lhalf = tid & 1;
    const __nv_bfloat16* aRowH = g_xh + (size_t)sTok[lrow] * HID;
    const __nv_bfloat16* aRowL = g_xl + (size_t)sTok[lrow] * HID;
    const __nv_bfloat16* bRowH = (lrow < 64)
        ? g_gh + ((size_t)e * INTER_ + n0 + lrow) * HID
        : g_uh + ((size_t)e * INTER_ + n0 + lrow - 64) * HID;
    const __nv_bfloat16* bRowL = (lrow < 64)
        ? g_gl + ((size_t)e * INTER_ + n0 + lrow) * HID
        : g_ul + ((size_t)e * INTER_ + n0 + lrow - 64) * HID;
    const uint32_t so0 = swz(lrow, lhalf * 2);
    const uint32_t so1 = swz(lrow, lhalf * 2 + 1);
    const int ge0 = lhalf * 16, ge1 = lhalf * 16 + 8;

    const int wm = wid >> 2, wn = wid & 3;
    const int g  = lane >> 2, t4 = lane & 3;
    const int lg = lane >> 3, lr7 = lane & 7;

    int rowA[4], xA[4];
    #pragma unroll
    for (int mt = 0; mt < 4; mt++) {
        rowA[mt] = wm * 64 + mt * 16 + (lg & 1) * 8 + lr7;
        xA[mt]   = (rowA[mt] >> 1) & 3;
    }
    int rowB[2], xB[2];
    #pragma unroll
    for (int p = 0; p < 2; p++) {
        rowB[p] = wn * 32 + (2 * p + (lg >> 1)) * 8 + lr7;
        xB[p]   = (rowB[p] >> 1) & 3;
    }

    float acc[4][4][4];
    #pragma unroll
    for (int i = 0; i < 4; i++)
        #pragma unroll
        for (int j = 0; j < 4; j++)
            #pragma unroll
            for (int r = 0; r < 4; r++) acc[i][j][r] = 0.f;

    const int NT = HID / KT;   // 64

    // prologue: stages 0, 1
    #pragma unroll
    for (int s = 0; s < 2; s++) {
        uint32_t d = sb + SLOT(s);
        int k0 = s * KT;
        CP16(d + so0,             aRowH + k0 + ge0);
        CP16(d + so1,             aRowH + k0 + ge1);
        CP16(d + PLANE + so0,     aRowL + k0 + ge0);
        CP16(d + PLANE + so1,     aRowL + k0 + ge1);
        CP16(d + 2 * PLANE + so0, bRowH + k0 + ge0);
        CP16(d + 2 * PLANE + so1, bRowH + k0 + ge1);
        CP16(d + 3 * PLANE + so0, bRowL + k0 + ge0);
        CP16(d + 3 * PLANE + so1, bRowL + k0 + ge1);
        CP_COMMIT();
    }

    int slot = 0, wslot = 2;
    for (int t = 0; t < NT; t++) {
        if (t < NT - 1) { CP_WAIT(1); } else { CP_WAIT(0); }
        __syncthreads();
        if (t + 2 < NT) {
            uint32_t d = sb + SLOT(wslot);
            int k0 = (t + 2) * KT;
            CP16(d + so0,             aRowH + k0 + ge0);
            CP16(d + so1,             aRowH + k0 + ge1);
            CP16(d + PLANE + so0,     aRowL + k0 + ge0);
            CP16(d + PLANE + so1,     aRowL + k0 + ge1);
            CP16(d + 2 * PLANE + so0, bRowH + k0 + ge0);
            CP16(d + 2 * PLANE + so1, bRowH + k0 + ge1);
            CP16(d + 3 * PLANE + so0, bRowL + k0 + ge0);
            CP16(d + 3 * PLANE + so1, bRowL + k0 + ge1);
            CP_COMMIT();
        }
        const uint32_t sa = sb + SLOT(slot);
        #pragma unroll
        for (int ks = 0; ks < 2; ks++) {
            const int cA = ks * 2 + (lg >> 1);
            const int cB = ks * 2 + (lg & 1);
            uint32_t bh[2][4], bl[2][4];
            #pragma unroll
            for (int p = 0; p < 2; p++) {
                uint32_t ab = sa + 2 * PLANE + (rowB[p] << 6) + (((cB ^ xB[p])) << 4);
                ldm_x4(bh[p], ab);
                ldm_x4(bl[p], ab + PLANE);
            }
            #pragma unroll
            for (int mt = 0; mt < 4; mt++) {
                uint32_t aa = sa + (rowA[mt] << 6) + (((cA ^ xA[mt])) << 4);
                uint32_t ah[4], al[4];
                ldm_x4(ah, aa);
                ldm_x4(al, aa + PLANE);
                #pragma unroll
                for (int nt = 0; nt < 4; nt++) {
                    const uint32_t* BH = &bh[nt >> 1][(nt & 1) * 2];
                    const uint32_t* BL = &bl[nt >> 1][(nt & 1) * 2];
                    mma_bf16(acc[mt][nt], al, BH);
                    mma_bf16(acc[mt][nt], ah, BL);
                    mma_bf16(acc[mt][nt], ah, BH);
                }
            }
        }
        slot  = (slot  == 2) ? 0 : slot + 1;
        wslot = (wslot == 2) ? 0 : wslot + 1;
    }
    __syncthreads();   // stages reused as Cs below

    // stage accumulators to smem, SwiGLU-combine, split to hi/lo planes
    float* Cs = (float*)(smem + SM_BUF);
    #pragma unroll
    for (int mt = 0; mt < 4; mt++) {
        #pragma unroll
        for (int nt = 0; nt < 4; nt++) {
            int row = wm * 64 + mt * 16 + g;
            int col = wn * 32 + nt * 8 + t4 * 2;
            *reinterpret_cast<float2*>(&Cs[row * CS_STRIDE + col]) =
                make_float2(acc[mt][nt][0], acc[mt][nt][1]);
            *reinterpret_cast<float2*>(&Cs[(row + 8) * CS_STRIDE + col]) =
                make_float2(acc[mt][nt][2], acc[mt][nt][3]);
        }
    }
    __syncthreads();

    const int jj = (tid & 15) * 4;
    const int rb = (tid >> 4) * 8;
    #pragma unroll
    for (int mm = 0; mm < 8; mm++) {
        int m = rb + mm;
        if (m0 + m >= cnt) continue;
        float w = sW[m];
        float4 gv = *reinterpret_cast<const float4*>(&Cs[m * CS_STRIDE + jj]);
        float4 uv = *reinterpret_cast<const float4*>(&Cs[m * CS_STRIDE + 64 + jj]);
        float o0 = (gv.x / (1.f + __expf(-gv.x))) * uv.x * w;
        float o1 = (gv.y / (1.f + __expf(-gv.y))) * uv.y * w;
        float o2 = (gv.z / (1.f + __expf(-gv.z))) * uv.z * w;
        float o3 = (gv.w / (1.f + __expf(-gv.w))) * uv.w * w;
        float r0, r1, r2, r3;
        uint2 H, L;
        H.x = packhl(o0, o1, r0, r1);
        H.y = packhl(o2, o3, r2, r3);
        L.x = packlo(r0, r1);
        L.y = packlo(r2, r3);
        size_t idx = (size_t)(base + m0 + m) * INTER_ + n0 + jj;
        *reinterpret_cast<uint2*>(&g_ih[idx]) = H;
        *reinterpret_cast<uint2*>(&g_il[idx]) = L;
    }
}

// ---------------- GEMM 2: down, 3x-bf16, 3-stage + dense store ------------
__global__ __launch_bounds__(256, 2)
void gemm_down_mma(void) {
    const int e   = blockIdx.z;
    const int cnt = g_counts[e];
    const int m0  = blockIdx.y * 128;
    if (m0 >= cnt) return;
    const int base = g_offsets[e];
    const int n0   = blockIdx.x * 128;

    extern __shared__ char smem[];
    const uint32_t sb = smem_u32(smem);

    const int tid  = threadIdx.x;
    const int wid  = tid >> 5;
    const int lane = tid & 31;

    const int lrow  = tid >> 1;
    const int lhalf = tid & 1;
    int ar = base + m0 + lrow; if (ar > NSLOT - 1) ar = NSLOT - 1;
    const __nv_bfloat16* aRowH = g_ih + (size_t)ar * INTER_;
    const __nv_bfloat16* aRowL = g_il + (size_t)ar * INTER_;
    const __nv_bfloat16* bRowH = g_dh + ((size_t)e * HID + n0 + lrow) * INTER_;
    const __nv_bfloat16* bRowL = g_dl + ((size_t)e * HID + n0 + lrow) * INTER_;
    const uint32_t so0 = swz(lrow, lhalf * 2);
    const uint32_t so1 = swz(lrow, lhalf * 2 + 1);
    const int ge0 = lhalf * 16, ge1 = lhalf * 16 + 8;

    const int wm = wid >> 2, wn = wid & 3;
    const int g  = lane >> 2, t4 = lane & 3;
    const int lg = lane >> 3, lr7 = lane & 7;

    int rowA[4], xA[4];
    #pragma unroll
    for (int mt = 0; mt < 4; mt++) {
        rowA[mt] = wm * 64 + mt * 16 + (lg & 1) * 8 + lr7;
        xA[mt]   = (rowA[mt] >> 1) & 3;
    }
    int rowB[2], xB[2];
    #pragma unroll
    for (int p = 0; p < 2; p++) {
        rowB[p] = wn * 32 + (2 * p + (lg >> 1)) * 8 + lr7;
        xB[p]   = (rowB[p] >> 1) & 3;
    }

    float acc[4][4][4];
    #pragma unroll
    for (int i = 0; i < 4; i++)
        #pragma unroll
        for (int j = 0; j < 4; j++)
            #pragma unroll
            for (int r = 0; r < 4; r++) acc[i][j][r] = 0.f;

    const int NT = INTER_ / KT;   // 32

    #pragma unroll
    for (int s = 0; s < 2; s++) {
        uint32_t d = sb + SLOT(s);
        int k0 = s * KT;
        CP16(d + so0,             aRowH + k0 + ge0);
        CP16(d + so1,             aRowH + k0 + ge1);
        CP16(d + PLANE + so0,     aRowL + k0 + ge0);
        CP16(d + PLANE + so1,     aRowL + k0 + ge1);
        CP16(d + 2 * PLANE + so0, bRowH + k0 + ge0);
        CP16(d + 2 * PLANE + so1, bRowH + k0 + ge1);
        CP16(d + 3 * PLANE + so0, bRowL + k0 + ge0);
        CP16(d + 3 * PLANE + so1, bRowL + k0 + ge1);
        CP_COMMIT();
    }

    int slot = 0, wslot = 2;
    for (int t = 0; t < NT; t++) {
        if (t < NT - 1) { CP_WAIT(1); } else { CP_WAIT(0); }
        __syncthreads();
        if (t + 2 < NT) {
            uint32_t d = sb + SLOT(wslot);
            int k0 = (t + 2) * KT;
            CP16(d + so0,             aRowH + k0 + ge0);
            CP16(d + so1,             aRowH + k0 + ge1);
            CP16(d + PLANE + so0,     aRowL + k0 + ge0);
            CP16(d + PLANE + so1,     aRowL + k0 + ge1);
            CP16(d + 2 * PLANE + so0, bRowH + k0 + ge0);
            CP16(d + 2 * PLANE + so1, bRowH + k0 + ge1);
            CP16(d + 3 * PLANE + so0, bRowL + k0 + ge0);
            CP16(d + 3 * PLANE + so1, bRowL + k0 + ge1);
            CP_COMMIT();
        }
        const uint32_t sa = sb + SLOT(slot);
        #pragma unroll
        for (int ks = 0; ks < 2; ks++) {
            const int cA = ks * 2 + (lg >> 1);
            const int cB = ks * 2 + (lg & 1);
            uint32_t bh[2][4], bl[2][4];
            #pragma unroll
            for (int p = 0; p < 2; p++) {
                uint32_t ab = sa + 2 * PLANE + (rowB[p] << 6) + (((cB ^ xB[p])) << 4);
                ldm_x4(bh[p], ab);
                ldm_x4(bl[p], ab + PLANE);
            }
            #pragma unroll
            for (int mt = 0; mt < 4; mt++) {
                uint32_t aa = sa + (rowA[mt] << 6) + (((cA ^ xA[mt])) << 4);
                uint32_t ah[4], al[4];
                ldm_x4(ah, aa);
                ldm_x4(al, aa + PLANE);
                #pragma unroll
                for (int nt = 0; nt < 4; nt++) {
                    const uint32_t* BH = &bh[nt >> 1][(nt & 1) * 2];
                    const uint32_t* BL = &bl[nt >> 1][(nt & 1) * 2];
                    mma_bf16(acc[mt][nt], al, BH);
                    mma_bf16(acc[mt][nt], ah, BL);
                    mma_bf16(acc[mt][nt], ah, BH);
                }
            }
        }
        slot  = (slot  == 2) ? 0 : slot + 1;
        wslot = (wslot == 2) ? 0 : wslot + 1;
    }

    // dense store to g_dout (sorted slot order)
    #pragma unroll
    for (int mt = 0; mt < 4; mt++) {
        int row0 = wm * 64 + mt * 16 + g;
        int row1 = row0 + 8;
        bool v0 = (m0 + row0 < cnt);
        bool v1 = (m0 + row1 < cnt);
        float* o0 = g_dout + (size_t)(base + m0 + row0) * HID + n0;
        float* o1 = g_dout + (size_t)(base + m0 + row1) * HID + n0;
        #pragma unroll
        for (int nt = 0; nt < 4; nt++) {
            int col = wn * 32 + nt * 8 + t4 * 2;
            if (v0) *reinterpret_cast<float2*>(&o0[col]) =
                        make_float2(acc[mt][nt][0], acc[mt][nt][1]);
            if (v1) *reinterpret_cast<float2*>(&o1[col]) =
                        make_float2(acc[mt][nt][2], acc[mt][nt][3]);
        }
    }
}

// ---------------- launch ----------------
extern "C" void kernel_launch(void* const* d_in, const int* in_sizes, int n_in,
                              void* d_out, int out_size) {
    const float* x    = (const float*)d_in[0];
    const int*   idxw = (const int*)d_in[1];
    const float* wts  = (const float*)d_in[2];
    const float* gate = (const float*)d_in[3];
    const float* up   = (const float*)d_in[4];
    const float* down = (const float*)d_in[5];
    float* out = (float*)d_out;

    cudaFuncSetAttribute(gemm_gu_mma,   cudaFuncAttributeMaxDynamicSharedMemorySize, SM_TOTAL);
    cudaFuncSetAttribute(gemm_down_mma, cudaFuncAttributeMaxDynamicSharedMemorySize, SM_TOTAL);

    __nv_bfloat16 *xh, *xl, *gh, *gl, *uh, *ul, *dh, *dl;
    cudaGetSymbolAddress((void**)&xh, g_xh);
    cudaGetSymbolAddress((void**)&xl, g_xl);
    cudaGetSymbolAddress((void**)&gh, g_gh);
    cudaGetSymbolAddress((void**)&gl, g_gl);
    cudaGetSymbolAddress((void**)&uh, g_uh);
    cudaGetSymbolAddress((void**)&ul, g_ul);
    cudaGetSymbolAddress((void**)&dh, g_dh);
    cudaGetSymbolAddress((void**)&dl, g_dl);

    route_kernel<<<1, 256>>>(idxw, wts);
    {
        int total = 3 * (NEXP * INTER_ * HID / 4) + NTOK * HID / 4;
        split_all<<<(total + 255) / 256, 256>>>(
            (const float4*)x, (const float4*)gate, (const float4*)up, (const float4*)down,
            (uint2*)xh, (uint2*)xl, (uint2*)gh, (uint2*)gl,
            (uint2*)uh, (uint2*)ul, (uint2*)dh, (uint2*)dl);
    }
    {
        dim3 grid(INTER_ / 64, NSLOT / 128, NEXP);
        gemm_gu_mma<<<grid, 256, SM_TOTAL>>>();
    }
    {
        dim3 grid(HID / 128, NSLOT / 128, NEXP);
        gemm_down_mma<<<grid, 256, SM_TOTAL>>>();
    }
    {
        int ng = NTOK * HID / 4;
        gather_kernel<<<(ng + 255) / 256, 256>>>((float4*)out);
    }
}

// round 10
// speedup vs baseline: 1.1261x; 1.0115x over previous
#include <cuda_runtime.h>
#include <cuda_bf16.h>
#include <math.h>
#include <stdint.h>

// Problem constants
#define NTOK   2048
#define HID    2048
#define INTER_ 1024
#define NEXP   8
#define TOPK   2
#define NSLOT  (NTOK * TOPK)

// Block: 512 thr (16 warps, 2x8), C = 128x256, warp tile 64x32, k-tile 32.
// SMEM: 4 stages, XOR-swizzled 64B rows. Stage: AH,AL (8KB) + BH,BL (16KB) = 48KB.
#define KT      32
#define PLANE_A 8192                 // 128 rows * 64B
#define PLANE_B 16384                // 256 rows * 64B
#define STAGE   (2 * PLANE_A + 2 * PLANE_B)   // 49152
#define SM_BUF  1024
#define SLOT(s)   (SM_BUF + (s) * STAGE)
#define OFF_AH  0
#define OFF_AL  PLANE_A
#define OFF_BH  (2 * PLANE_A)
#define OFF_BL  (2 * PLANE_A + PLANE_B)
#define SM_TOTAL (SM_BUF + 4 * STAGE)        // 197632
#define CS_STRIDE 264

// -------- device scratch --------
__device__ int   g_counts[NEXP];
__device__ int   g_offsets[NEXP];
__device__ int   g_token[NSLOT];
__device__ int   g_pos[NSLOT];
__device__ float g_weight[NSLOT];
__device__ float g_dout[(size_t)NSLOT * HID];
__device__ __nv_bfloat16 g_xh[(size_t)NTOK * HID];
__device__ __nv_bfloat16 g_xl[(size_t)NTOK * HID];
__device__ __nv_bfloat16 g_gh[(size_t)NEXP * INTER_ * HID];
__device__ __nv_bfloat16 g_gl[(size_t)NEXP * INTER_ * HID];
__device__ __nv_bfloat16 g_uh[(size_t)NEXP * INTER_ * HID];
__device__ __nv_bfloat16 g_ul[(size_t)NEXP * INTER_ * HID];
__device__ __nv_bfloat16 g_dh[(size_t)NEXP * HID * INTER_];
__device__ __nv_bfloat16 g_dl[(size_t)NEXP * HID * INTER_];
__device__ __nv_bfloat16 g_ih[(size_t)NSLOT * INTER_];
__device__ __nv_bfloat16 g_il[(size_t)NSLOT * INTER_];

// ---------------- helpers ----------------
__device__ __forceinline__ uint32_t smem_u32(const void* p) {
    uint32_t a;
    asm("{ .reg .u64 t; cvta.to.shared.u64 t, %1; cvt.u32.u64 %0, t; }" : "=r"(a) : "l"(p));
    return a;
}
#define CP16(sm, gm) asm volatile("cp.async.cg.shared.global [%0], [%1], 16;" :: "r"(sm), "l"(gm))
#define CP_COMMIT()  asm volatile("cp.async.commit_group;" ::: "memory")
#define CP_WAIT(n)   asm volatile("cp.async.wait_group %0;" :: "n"(n) : "memory")

__device__ __forceinline__ void mma_bf16(float* c, const uint32_t* a, const uint32_t* b) {
    asm volatile(
        "mma.sync.aligned.m16n8k16.row.col.f32.bf16.bf16.f32 "
        "{%0,%1,%2,%3}, {%4,%5,%6,%7}, {%8,%9}, {%0,%1,%2,%3};\n"
        : "+f"(c[0]), "+f"(c[1]), "+f"(c[2]), "+f"(c[3])
        : "r"(a[0]), "r"(a[1]), "r"(a[2]), "r"(a[3]), "r"(b[0]), "r"(b[1]));
}
__device__ __forceinline__ void ldm_x4(uint32_t* r, uint32_t addr) {
    asm volatile("ldmatrix.sync.aligned.m8n8.x4.shared.b16 {%0,%1,%2,%3}, [%4];"
        : "=r"(r[0]), "=r"(r[1]), "=r"(r[2]), "=r"(r[3]) : "r"(addr));
}

// swizzled byte offset within a plane: 64B rows, 16B chunks, chunk ^= (row>>1)&3
__device__ __forceinline__ uint32_t swz(int row, int chunk) {
    return (uint32_t)((row << 6) + (((chunk ^ ((row >> 1) & 3))) << 4));
}

__device__ __forceinline__ uint32_t packhl(float a, float b, float& ra, float& rb) {
    __nv_bfloat16 ha = __float2bfloat16(a);
    __nv_bfloat16 hb = __float2bfloat16(b);
    ra = a - __bfloat162float(ha);
    rb = b - __bfloat162float(hb);
    __nv_bfloat162 p = __halves2bfloat162(ha, hb);
    return *reinterpret_cast<uint32_t*>(&p);
}
__device__ __forceinline__ uint32_t packlo(float a, float b) {
    __nv_bfloat162 p = __halves2bfloat162(__float2bfloat16(a), __float2bfloat16(b));
    return *reinterpret_cast<uint32_t*>(&p);
}

// ---------------- fused split ----------------
__global__ void split_all(const float4* __restrict__ xs,
                          const float4* __restrict__ gs,
                          const float4* __restrict__ us,
                          const float4* __restrict__ ds,
                          uint2* __restrict__ xh, uint2* __restrict__ xl,
                          uint2* __restrict__ gh, uint2* __restrict__ gl,
                          uint2* __restrict__ uh, uint2* __restrict__ ul,
                          uint2* __restrict__ dh, uint2* __restrict__ dl) {
    const int nw = NEXP * INTER_ * HID / 4;
    const int nx = NTOK * HID / 4;
    int i = blockIdx.x * blockDim.x + threadIdx.x;
    const float4* src; uint2 *H, *L; int j;
    if (i < nw)               { src = gs; H = gh; L = gl; j = i; }
    else if (i < 2 * nw)      { src = us; H = uh; L = ul; j = i - nw; }
    else if (i < 3 * nw)      { src = ds; H = dh; L = dl; j = i - 2 * nw; }
    else if (i < 3 * nw + nx) { src = xs; H = xh; L = xl; j = i - 3 * nw; }
    else return;
    float4 v = src[j];
    float rx, ry, rz, rw;
    uint2 Hv, Lv;
    Hv.x = packhl(v.x, v.y, rx, ry);
    Hv.y = packhl(v.z, v.w, rz, rw);
    Lv.x = packlo(rx, ry);
    Lv.y = packlo(rz, rw);
    H[j] = Hv;
    L[j] = Lv;
}

// ---------------- routing ----------------
__global__ void route_kernel(const int* __restrict__ idxw,
                             const float* __restrict__ wts) {
    __shared__ int cnt[NEXP], off[NEXP], cur[NEXP];
    __shared__ int not64;
    int tid = threadIdx.x;
    if (tid < NEXP) { cnt[tid] = 0; cur[tid] = 0; }
    if (tid == 0) not64 = 0;
    __syncthreads();
    int any = 0;
    for (int i = 2 * tid + 1; i < NSLOT; i += 2 * blockDim.x) any |= idxw[i];
    if (any) atomicOr(&not64, 1);
    __syncthreads();
    const int is64 = !not64;
    for (int s = tid; s < NSLOT; s += blockDim.x) {
        int e = is64 ? idxw[2 * s] : idxw[s];
        atomicAdd(&cnt[e], 1);
    }
    __syncthreads();
    if (tid == 0) {
        int acc = 0;
        for (int e = 0; e < NEXP; e++) {
            off[e] = acc; g_offsets[e] = acc; g_counts[e] = cnt[e];
            acc += cnt[e];
        }
    }
    __syncthreads();
    for (int s = tid; s < NSLOT; s += blockDim.x) {
        int e = is64 ? idxw[2 * s] : idxw[s];
        int p = off[e] + atomicAdd(&cur[e], 1);
        g_token[p]  = s >> 1;
        g_weight[p] = wts[s];
        g_pos[s]    = p;
    }
}

// ---------------- gather ----------------
__global__ void gather_kernel(float4* __restrict__ out) {
    int i = blockIdx.x * blockDim.x + threadIdx.x;
    if (i >= NTOK * HID / 4) return;
    int t = i / (HID / 4);
    int h = i - t * (HID / 4);
    const float4* r0 = (const float4*)(g_dout + (size_t)g_pos[2 * t] * HID) + h;
    const float4* r1 = (const float4*)(g_dout + (size_t)g_pos[2 * t + 1] * HID) + h;
    float4 a = *r0, b = *r1;
    out[i] = make_float4(a.x + b.x, a.y + b.y, a.z + b.z, a.w + b.w);
}

// ---------------- GEMM 1: gate+up, C=128x(128g|128u), 4-stage ------------
__global__ __launch_bounds__(512, 1)
void gemm_gu_mma(void) {
    const int e   = blockIdx.z;
    const int cnt = g_counts[e];
    const int m0  = blockIdx.y * 128;
    if (m0 >= cnt) return;
    const int base = g_offsets[e];
    const int n0   = blockIdx.x * 128;

    extern __shared__ char smem[];
    const uint32_t sb = smem_u32(smem);
    int*   sTok = (int*)smem;
    float* sW   = (float*)(smem + 512);

    const int tid  = threadIdx.x;
    const int wid  = tid >> 5;
    const int lane = tid & 31;

    if (tid < 128) {
        int m = m0 + tid;
        int r = base + (m < cnt ? m : cnt - 1);
        sTok[tid] = g_token[r];
        sW[tid]   = (m < cnt) ? g_weight[r] : 0.f;
    }
    __syncthreads();

    // loaders
    const int lrow  = tid >> 1;        // 0..255
    const int lhalf = tid & 1;
    const int ge0 = lhalf * 16, ge1 = lhalf * 16 + 8;
    // A: threads 0..255 (rows 0..127)
    const __nv_bfloat16* aRowH = g_xh + (size_t)sTok[lrow & 127] * HID;
    const __nv_bfloat16* aRowL = g_xl + (size_t)sTok[lrow & 127] * HID;
    const uint32_t soA0 = swz(lrow & 127, lhalf * 2);
    const uint32_t soA1 = swz(lrow & 127, lhalf * 2 + 1);
    // B: all 512 threads, rows 0..255 (0-127 gate, 128-255 up)
    const __nv_bfloat16* bRowH = (lrow < 128)
        ? g_gh + ((size_t)e * INTER_ + n0 + lrow) * HID
        : g_uh + ((size_t)e * INTER_ + n0 + lrow - 128) * HID;
    const __nv_bfloat16* bRowL = (lrow < 128)
        ? g_gl + ((size_t)e * INTER_ + n0 + lrow) * HID
        : g_ul + ((size_t)e * INTER_ + n0 + lrow - 128) * HID;
    const uint32_t soB0 = swz(lrow, lhalf * 2);
    const uint32_t soB1 = swz(lrow, lhalf * 2 + 1);
    const bool doA = (tid < 256);

    const int wm = wid >> 3, wn = wid & 7;      // 2 x 8 warps
    const int g  = lane >> 2, t4 = lane & 3;
    const int lg = lane >> 3, lr7 = lane & 7;

    int rowA[4], xA[4];
    #pragma unroll
    for (int mt = 0; mt < 4; mt++) {
        rowA[mt] = wm * 64 + mt * 16 + (lg & 1) * 8 + lr7;
        xA[mt]   = (rowA[mt] >> 1) & 3;
    }
    int rowB[2], xB[2];
    #pragma unroll
    for (int p = 0; p < 2; p++) {
        rowB[p] = wn * 32 + (2 * p + (lg >> 1)) * 8 + lr7;
        xB[p]   = (rowB[p] >> 1) & 3;
    }

    float acc[4][4][4];
    #pragma unroll
    for (int i = 0; i < 4; i++)
        #pragma unroll
        for (int j = 0; j < 4; j++)
            #pragma unroll
            for (int r = 0; r < 4; r++) acc[i][j][r] = 0.f;

    const int NT = HID / KT;   // 64

    // prologue: stages 0..2
    #pragma unroll
    for (int s = 0; s < 3; s++) {
        uint32_t d = sb + SLOT(s);
        int k0 = s * KT;
        if (doA) {
            CP16(d + OFF_AH + soA0, aRowH + k0 + ge0);
            CP16(d + OFF_AH + soA1, aRowH + k0 + ge1);
            CP16(d + OFF_AL + soA0, aRowL + k0 + ge0);
            CP16(d + OFF_AL + soA1, aRowL + k0 + ge1);
        }
        CP16(d + OFF_BH + soB0, bRowH + k0 + ge0);
        CP16(d + OFF_BH + soB1, bRowH + k0 + ge1);
        CP16(d + OFF_BL + soB0, bRowL + k0 + ge0);
        CP16(d + OFF_BL + soB1, bRowL + k0 + ge1);
        CP_COMMIT();
    }

    int slot = 0, wslot = 3;
    for (int t = 0; t < NT; t++) {
        if (t + 2 < NT)      { CP_WAIT(2); }
        else if (t + 1 < NT) { CP_WAIT(1); }
        else                 { CP_WAIT(0); }
        __syncthreads();
        if (t + 3 < NT) {
            uint32_t d = sb + SLOT(wslot);
            int k0 = (t + 3) * KT;
            if (doA) {
                CP16(d + OFF_AH + soA0, aRowH + k0 + ge0);
                CP16(d + OFF_AH + soA1, aRowH + k0 + ge1);
                CP16(d + OFF_AL + soA0, aRowL + k0 + ge0);
                CP16(d + OFF_AL + soA1, aRowL + k0 + ge1);
            }
            CP16(d + OFF_BH + soB0, bRowH + k0 + ge0);
            CP16(d + OFF_BH + soB1, bRowH + k0 + ge1);
            CP16(d + OFF_BL + soB0, bRowL + k0 + ge0);
            CP16(d + OFF_BL + soB1, bRowL + k0 + ge1);
            CP_COMMIT();
        }
        const uint32_t sa = sb + SLOT(slot);
        #pragma unroll
        for (int ks = 0; ks < 2; ks++) {
            const int cA = ks * 2 + (lg >> 1);
            const int cB = ks * 2 + (lg & 1);
            uint32_t bh[2][4], bl[2][4];
            #pragma unroll
            for (int p = 0; p < 2; p++) {
                uint32_t ab = sa + OFF_BH + (rowB[p] << 6) + (((cB ^ xB[p])) << 4);
                ldm_x4(bh[p], ab);
                ldm_x4(bl[p], ab + PLANE_B);
            }
            #pragma unroll
            for (int mt = 0; mt < 4; mt++) {
                uint32_t aa = sa + OFF_AH + (rowA[mt] << 6) + (((cA ^ xA[mt])) << 4);
                uint32_t ah[4], al[4];
                ldm_x4(ah, aa);
                ldm_x4(al, aa + PLANE_A);
                #pragma unroll
                for (int nt = 0; nt < 4; nt++) {
                    const uint32_t* BH = &bh[nt >> 1][(nt & 1) * 2];
                    const uint32_t* BL = &bl[nt >> 1][(nt & 1) * 2];
                    mma_bf16(acc[mt][nt], al, BH);
                    mma_bf16(acc[mt][nt], ah, BL);
                    mma_bf16(acc[mt][nt], ah, BH);
                }
            }
        }
        slot  = (slot  == 3) ? 0 : slot + 1;
        wslot = (wslot == 3) ? 0 : wslot + 1;
    }
    __syncthreads();   // stages reused as Cs below

    // stage C to smem: cols 0-127 gate, 128-255 up
    float* Cs = (float*)(smem + SM_BUF);
    #pragma unroll
    for (int mt = 0; mt < 4; mt++) {
        #pragma unroll
        for (int nt = 0; nt < 4; nt++) {
            int row = wm * 64 + mt * 16 + g;
            int col = wn * 32 + nt * 8 + t4 * 2;
            *reinterpret_cast<float2*>(&Cs[row * CS_STRIDE + col]) =
                make_float2(acc[mt][nt][0], acc[mt][nt][1]);
            *reinterpret_cast<float2*>(&Cs[(row + 8) * CS_STRIDE + col]) =
                make_float2(acc[mt][nt][2], acc[mt][nt][3]);
        }
    }
    __syncthreads();

    const int jj = (tid & 31) * 4;       // 0..124
    const int rb = (tid >> 5) * 8;       // 0..120
    #pragma unroll
    for (int mm = 0; mm < 8; mm++) {
        int m = rb + mm;
        if (m0 + m >= cnt) continue;
        float w = sW[m];
        float4 gv = *reinterpret_cast<const float4*>(&Cs[m * CS_STRIDE + jj]);
        float4 uv = *reinterpret_cast<const float4*>(&Cs[m * CS_STRIDE + 128 + jj]);
        float o0 = (gv.x / (1.f + __expf(-gv.x))) * uv.x * w;
        float o1 = (gv.y / (1.f + __expf(-gv.y))) * uv.y * w;
        float o2 = (gv.z / (1.f + __expf(-gv.z))) * uv.z * w;
        float o3 = (gv.w / (1.f + __expf(-gv.w))) * uv.w * w;
        float r0, r1, r2, r3;
        uint2 H, L;
        H.x = packhl(o0, o1, r0, r1);
        H.y = packhl(o2, o3, r2, r3);
        L.x = packlo(r0, r1);
        L.y = packlo(r2, r3);
        size_t idx = (size_t)(base + m0 + m) * INTER_ + n0 + jj;
        *reinterpret_cast<uint2*>(&g_ih[idx]) = H;
        *reinterpret_cast<uint2*>(&g_il[idx]) = L;
    }
}

// ---------------- GEMM 2: down, C=128x256, 4-stage + dense store ---------
__global__ __launch_bounds__(512, 1)
void gemm_down_mma(void) {
    const int e   = blockIdx.z;
    const int cnt = g_counts[e];
    const int m0  = blockIdx.y * 128;
    if (m0 >= cnt) return;
    const int base = g_offsets[e];
    const int n0   = blockIdx.x * 256;

    extern __shared__ char smem[];
    const uint32_t sb = smem_u32(smem);

    const int tid  = threadIdx.x;
    const int wid  = tid >> 5;
    const int lane = tid & 31;

    const int lrow  = tid >> 1;
    const int lhalf = tid & 1;
    const int ge0 = lhalf * 16, ge1 = lhalf * 16 + 8;
    int ar = base + m0 + (lrow & 127); if (ar > NSLOT - 1) ar = NSLOT - 1;
    const __nv_bfloat16* aRowH = g_ih + (size_t)ar * INTER_;
    const __nv_bfloat16* aRowL = g_il + (size_t)ar * INTER_;
    const uint32_t soA0 = swz(lrow & 127, lhalf * 2);
    const uint32_t soA1 = swz(lrow & 127, lhalf * 2 + 1);
    const __nv_bfloat16* bRowH = g_dh + ((size_t)e * HID + n0 + lrow) * INTER_;
    const __nv_bfloat16* bRowL = g_dl + ((size_t)e * HID + n0 + lrow) * INTER_;
    const uint32_t soB0 = swz(lrow, lhalf * 2);
    const uint32_t soB1 = swz(lrow, lhalf * 2 + 1);
    const bool doA = (tid < 256);

    const int wm = wid >> 3, wn = wid & 7;
    const int g  = lane >> 2, t4 = lane & 3;
    const int lg = lane >> 3, lr7 = lane & 7;

    int rowA[4], xA[4];
    #pragma unroll
    for (int mt = 0; mt < 4; mt++) {
        rowA[mt] = wm * 64 + mt * 16 + (lg & 1) * 8 + lr7;
        xA[mt]   = (rowA[mt] >> 1) & 3;
    }
    int rowB[2], xB[2];
    #pragma unroll
    for (int p = 0; p < 2; p++) {
        rowB[p] = wn * 32 + (2 * p + (lg >> 1)) * 8 + lr7;
        xB[p]   = (rowB[p] >> 1) & 3;
    }

    float acc[4][4][4];
    #pragma unroll
    for (int i = 0; i < 4; i++)
        #pragma unroll
        for (int j = 0; j < 4; j++)
            #pragma unroll
            for (int r = 0; r < 4; r++) acc[i][j][r] = 0.f;

    const int NT = INTER_ / KT;   // 32

    #pragma unroll
    for (int s = 0; s < 3; s++) {
        uint32_t d = sb + SLOT(s);
        int k0 = s * KT;
        if (doA) {
            CP16(d + OFF_AH + soA0, aRowH + k0 + ge0);
            CP16(d + OFF_AH + soA1, aRowH + k0 + ge1);
            CP16(d + OFF_AL + soA0, aRowL + k0 + ge0);
            CP16(d + OFF_AL + soA1, aRowL + k0 + ge1);
        }
        CP16(d + OFF_BH + soB0, bRowH + k0 + ge0);
        CP16(d + OFF_BH + soB1, bRowH + k0 + ge1);
        CP16(d + OFF_BL + soB0, bRowL + k0 + ge0);
        CP16(d + OFF_BL + soB1, bRowL + k0 + ge1);
        CP_COMMIT();
    }

    int slot = 0, wslot = 3;
    for (int t = 0; t < NT; t++) {
        if (t + 2 < NT)      { CP_WAIT(2); }
        else if (t + 1 < NT) { CP_WAIT(1); }
        else                 { CP_WAIT(0); }
        __syncthreads();
        if (t + 3 < NT) {
            uint32_t d = sb + SLOT(wslot);
            int k0 = (t + 3) * KT;
            if (doA) {
                CP16(d + OFF_AH + soA0, aRowH + k0 + ge0);
                CP16(d + OFF_AH + soA1, aRowH + k0 + ge1);
                CP16(d + OFF_AL + soA0, aRowL + k0 + ge0);
                CP16(d + OFF_AL + soA1, aRowL + k0 + ge1);
            }
            CP16(d + OFF_BH + soB0, bRowH + k0 + ge0);
            CP16(d + OFF_BH + soB1, bRowH + k0 + ge1);
            CP16(d + OFF_BL + soB0, bRowL + k0 + ge0);
            CP16(d + OFF_BL + soB1, bRowL + k0 + ge1);
            CP_COMMIT();
        }
        const uint32_t sa = sb + SLOT(slot);
        #pragma unroll
        for (int ks = 0; ks < 2; ks++) {
            const int cA = ks * 2 + (lg >> 1);
            const int cB = ks * 2 + (lg & 1);
            uint32_t bh[2][4], bl[2][4];
            #pragma unroll
            for (int p = 0; p < 2; p++) {
                uint32_t ab = sa + OFF_BH + (rowB[p] << 6) + (((cB ^ xB[p])) << 4);
                ldm_x4(bh[p], ab);
                ldm_x4(bl[p], ab + PLANE_B);
            }
            #pragma unroll
            for (int mt = 0; mt < 4; mt++) {
                uint32_t aa = sa + OFF_AH + (rowA[mt] << 6) + (((cA ^ xA[mt])) << 4);
                uint32_t ah[4], al[4];
                ldm_x4(ah, aa);
                ldm_x4(al, aa + PLANE_A);
                #pragma unroll
                for (int nt = 0; nt < 4; nt++) {
                    const uint32_t* BH = &bh[nt >> 1][(nt & 1) * 2];
                    const uint32_t* BL = &bl[nt >> 1][(nt & 1) * 2];
                    mma_bf16(acc[mt][nt], al, BH);
                    mma_bf16(acc[mt][nt], ah, BL);
                    mma_bf16(acc[mt][nt], ah, BH);
                }
            }
        }
        slot  = (slot  == 3) ? 0 : slot + 1;
        wslot = (wslot == 3) ? 0 : wslot + 1;
    }

    // dense store to g_dout
    #pragma unroll
    for (int mt = 0; mt < 4; mt++) {
        int row0 = wm * 64 + mt * 16 + g;
        int row1 = row0 + 8;
        bool v0 = (m0 + row0 < cnt);
        bool v1 = (m0 + row1 < cnt);
        float* o0 = g_dout + (size_t)(base + m0 + row0) * HID + n0;
        float* o1 = g_dout + (size_t)(base + m0 + row1) * HID + n0;
        #pragma unroll
        for (int nt = 0; nt < 4; nt++) {
            int col = wn * 32 + nt * 8 + t4 * 2;
            if (v0) *reinterpret_cast<float2*>(&o0[col]) =
                        make_float2(acc[mt][nt][0], acc[mt][nt][1]);
            if (v1) *reinterpret_cast<float2*>(&o1[col]) =
                        make_float2(acc[mt][nt][2], acc[mt][nt][3]);
        }
    }
}

// ---------------- launch ----------------
extern "C" void kernel_launch(void* const* d_in, const int* in_sizes, int n_in,
                              void* d_out, int out_size) {
    const float* x    = (const float*)d_in[0];
    const int*   idxw = (const int*)d_in[1];
    const float* wts  = (const float*)d_in[2];
    const float* gate = (const float*)d_in[3];
    const float* up   = (const float*)d_in[4];
    const float* down = (const float*)d_in[5];
    float* out = (float*)d_out;

    cudaFuncSetAttribute(gemm_gu_mma,   cudaFuncAttributeMaxDynamicSharedMemorySize, SM_TOTAL);
    cudaFuncSetAttribute(gemm_down_mma, cudaFuncAttributeMaxDynamicSharedMemorySize, SM_TOTAL);

    __nv_bfloat16 *xh, *xl, *gh, *gl, *uh, *ul, *dh, *dl;
    cudaGetSymbolAddress((void**)&xh, g_xh);
    cudaGetSymbolAddress((void**)&xl, g_xl);
    cudaGetSymbolAddress((void**)&gh, g_gh);
    cudaGetSymbolAddress((void**)&gl, g_gl);
    cudaGetSymbolAddress((void**)&uh, g_uh);
    cudaGetSymbolAddress((void**)&ul, g_ul);
    cudaGetSymbolAddress((void**)&dh, g_dh);
    cudaGetSymbolAddress((void**)&dl, g_dl);

    route_kernel<<<1, 256>>>(idxw, wts);
    {
        int total = 3 * (NEXP * INTER_ * HID / 4) + NTOK * HID / 4;
        split_all<<<(total + 255) / 256, 256>>>(
            (const float4*)x, (const float4*)gate, (const float4*)up, (const float4*)down,
            (uint2*)xh, (uint2*)xl, (uint2*)gh, (uint2*)gl,
            (uint2*)uh, (uint2*)ul, (uint2*)dh, (uint2*)dl);
    }
    {
        dim3 grid(INTER_ / 128, NSLOT / 128, NEXP);
        gemm_gu_mma<<<grid, 512, SM_TOTAL>>>();
    }
    {
        dim3 grid(HID / 256, NSLOT / 128, NEXP);
        gemm_down_mma<<<grid, 512, SM_TOTAL>>>();
    }
    {
        int ng = NTOK * HID / 4;
        gather_kernel<<<(ng + 255) / 256, 256>>>((float4*)out);
    }
}